// round 14
// baseline (speedup 1.0000x reference)
#include <cuda_runtime.h>
#include <cuda_bf16.h>
#include <cuda_fp16.h>
#include <cstdint>

// ---------------------------------------------------------------------------
// GCN 2-layer encoder. CSR per call (overlapped with layer-1 GEMM); GEMM
// epilogue pre-scales rows by dinv so aggregation is a pure row-sum; fp16
// h / inter-layer activation; bf16x3 mma.sync GEMM with BM=64 (2 CTAs/SM).
// Serial layer schedule (R10 chunk pipeline regressed; reverted).
// ---------------------------------------------------------------------------

#define N_NODES 100000
#define N_EDGES 1600000
#define FDIM    128
#define SCAN_B  1024
#define SCAN_NB ((N_NODES + SCAN_B - 1) / SCAN_B)   // 98

__device__ int    g_is64;
__device__ int    g_deg[N_NODES];
__device__ int    g_pos[N_NODES];
__device__ int    g_off[N_NODES + 1];
__device__ int    g_bsum[SCAN_NB];
__device__ float  g_dinv[N_NODES];
__device__ int    g_csr[N_EDGES];
__device__ __half g_h[(size_t)N_NODES * FDIM];    // dinv-scaled GEMM output
__device__ __half g_yh[(size_t)N_NODES * FDIM];   // layer-1 activation (fp16)

// ---------------- detect dtype + zero counters (fused) ----------------
__global__ void dz_kernel(const unsigned int* __restrict__ w, int n) {
    int i = blockIdx.x * blockDim.x + threadIdx.x;
    if (i < n) g_deg[i] = 0;
    if (blockIdx.x == 0) {
        int z = (w[2 * threadIdx.x + 1] == 0u) ? 1 : 0;
        int total = __syncthreads_count(z);
        if (threadIdx.x == 0) g_is64 = (total == 256) ? 1 : 0;
    }
}

__device__ __forceinline__ int edge_at(const void* ei, long long idx, int n) {
    long long v = g_is64 ? ((const long long*)ei)[idx]
                         : (long long)((const int*)ei)[idx];
    int i = (int)v;
    if (i < 0) i = 0;
    if (i >= n) i = n - 1;
    return i;
}

// ---------------- CSR build ----------------

__global__ void deg_kernel(const void* __restrict__ ei, int E, int n) {
    int e = blockIdx.x * blockDim.x + threadIdx.x;
    if (e < E) atomicAdd(&g_deg[edge_at(ei, (long long)E + e, n)], 1);
}

// per-block scan of counts + dinv computation (fused)
__global__ void scan1_kernel(int n) {
    __shared__ int s[SCAN_B];
    int t = threadIdx.x;
    int i = blockIdx.x * SCAN_B + t;
    int v = 0;
    if (i < n) {
        v = g_deg[i];
        g_dinv[i] = rsqrtf((float)v + 1.0f);
    }
    s[t] = v;
    __syncthreads();
    for (int o = 1; o < SCAN_B; o <<= 1) {
        int x = (t >= o) ? s[t - o] : 0;
        __syncthreads();
        s[t] += x;
        __syncthreads();
    }
    if (i < n) g_off[i] = s[t] - v;
    if (t == SCAN_B - 1) g_bsum[blockIdx.x] = s[t];
}

// finalize offsets: every block redundantly scans the 98 block sums (L2-hot),
// adds its exclusive prefix, seeds the scatter cursor.
__global__ void scan3_kernel(int nb, int n, int E) {
    __shared__ int s[128];
    __shared__ int pre;
    int t = threadIdx.x;
    if (t < 128) {
        int v = (t < nb) ? g_bsum[t] : 0;
        s[t] = v;
    }
    __syncthreads();
    if (t < 128) {
        for (int o = 1; o < 128; o <<= 1) {
            int x = (t >= o) ? s[t - o] : 0;
            __syncthreads();
            s[t] += x;
            __syncthreads();
        }
        if (t == 0) pre = (blockIdx.x == 0) ? 0 : s[blockIdx.x - 1];
    } else {
        for (int o = 1; o < 128; o <<= 1) { __syncthreads(); __syncthreads(); }
    }
    __syncthreads();
    int base = pre;
    int i = blockIdx.x * SCAN_B + t;
    if (i < n) {
        int o = g_off[i] + base;
        g_off[i] = o;
        g_pos[i] = o;
    }
    if (i == n - 1) g_off[n] = E;
}

__global__ void scatter_kernel(const void* __restrict__ ei, int E, int n) {
    int e = blockIdx.x * blockDim.x + threadIdx.x;
    if (e < E) {
        int s = edge_at(ei, e, n);
        int d = edge_at(ei, (long long)E + e, n);
        g_csr[atomicAdd(&g_pos[d], 1)] = s;
    }
}

// ---------------- mma.sync bf16x3 GEMM, BM=64 ------------------------------
// g_h[M,128](fp16) = dinv[:,None] * (A @ W^T). A fp32 or fp16 g_yh.
// 512 threads, 16 warps (4x4), each warp a 16x32 C-tile. 2 CTAs/SM.

#define TROWB 272
#define ATSZ  (64 * TROWB)               // 17408 B per A tile
#define WTSZ  (128 * TROWB)              // 34816 B per W tile
#define AHI_O 0
#define ALO_O (ATSZ)
#define WHI_O (2 * ATSZ)
#define WLO_O (2 * ATSZ + WTSZ)
#define SM_TOT (2 * ATSZ + 2 * WTSZ)     // 104448 B dynamic smem

__device__ __forceinline__ uint32_t smem_u32(const void* p) {
    uint32_t a;
    asm("{ .reg .u64 t; cvta.to.shared.u64 t, %1; cvt.u32.u64 %0, t; }"
        : "=r"(a) : "l"(p));
    return a;
}

__device__ __forceinline__ uint32_t pack_bf2(__nv_bfloat16 a, __nv_bfloat16 b) {
    return (uint32_t)__bfloat16_as_ushort(a) | ((uint32_t)__bfloat16_as_ushort(b) << 16);
}

__device__ __forceinline__ void cvt_store(char* smem, int hi_off, int lo_off,
                                          int r, int c4, float4 v) {
    __nv_bfloat16 h0 = __float2bfloat16_rn(v.x);
    __nv_bfloat16 h1 = __float2bfloat16_rn(v.y);
    __nv_bfloat16 h2 = __float2bfloat16_rn(v.z);
    __nv_bfloat16 h3 = __float2bfloat16_rn(v.w);
    __nv_bfloat16 l0 = __float2bfloat16_rn(v.x - __bfloat162float(h0));
    __nv_bfloat16 l1 = __float2bfloat16_rn(v.y - __bfloat162float(h1));
    __nv_bfloat16 l2 = __float2bfloat16_rn(v.z - __bfloat162float(h2));
    __nv_bfloat16 l3 = __float2bfloat16_rn(v.w - __bfloat162float(h3));
    int off = r * TROWB + c4 * 2;
    uint2 hp; hp.x = pack_bf2(h0, h1); hp.y = pack_bf2(h2, h3);
    uint2 lp; lp.x = pack_bf2(l0, l1); lp.y = pack_bf2(l2, l3);
    *(uint2*)(smem + hi_off + off) = hp;
    *(uint2*)(smem + lo_off + off) = lp;
}

__device__ __forceinline__ void ldm_x4(uint32_t* r, uint32_t addr) {
    asm volatile("ldmatrix.sync.aligned.m8n8.x4.shared.b16 {%0,%1,%2,%3}, [%4];"
                 : "=r"(r[0]), "=r"(r[1]), "=r"(r[2]), "=r"(r[3]) : "r"(addr));
}

__device__ __forceinline__ void mma_bf16(float* c, const uint32_t* a,
                                         uint32_t b0, uint32_t b1) {
    asm volatile(
        "mma.sync.aligned.m16n8k16.row.col.f32.bf16.bf16.f32 "
        "{%0,%1,%2,%3}, {%4,%5,%6,%7}, {%8,%9}, {%0,%1,%2,%3};"
        : "+f"(c[0]), "+f"(c[1]), "+f"(c[2]), "+f"(c[3])
        : "r"(a[0]), "r"(a[1]), "r"(a[2]), "r"(a[3]), "r"(b0), "r"(b1));
}

__global__ __launch_bounds__(512, 2)
void gemm_mma_kernel(const float* __restrict__ Aopt, const float* __restrict__ W,
                     int M) {
    extern __shared__ char smem[];
    int tid = threadIdx.x;
    int wid = tid >> 5;
    int lane = tid & 31;
    int row0 = blockIdx.x * 64;
    int trows = (row0 + 64 <= M) ? 64 : (M - row0);

    // A tile (64 rows)
    for (int idx = tid; idx < 64 * 32; idx += 512) {
        int r = idx >> 5;
        int c4 = (idx & 31) << 2;
        float4 v = {0.f, 0.f, 0.f, 0.f};
        if (r < trows) {
            if (Aopt) {
                v = *(const float4*)(Aopt + (size_t)(row0 + r) * FDIM + c4);
            } else {
                uint2 pk = *(const uint2*)(g_yh + (size_t)(row0 + r) * FDIM + c4);
                float2 a = __half22float2(*(const __half2*)&pk.x);
                float2 b = __half22float2(*(const __half2*)&pk.y);
                v.x = a.x; v.y = a.y; v.z = b.x; v.w = b.y;
            }
        }
        cvt_store(smem, AHI_O, ALO_O, r, c4, v);
    }
    // W tile (128 rows)
    for (int idx = tid; idx < 128 * 32; idx += 512) {
        int r = idx >> 5;
        int c4 = (idx & 31) << 2;
        float4 wv = *(const float4*)(W + (size_t)r * FDIM + c4);
        cvt_store(smem, WHI_O, WLO_O, r, c4, wv);
    }
    __syncthreads();

    uint32_t sbase = smem_u32(smem);
    int warpM = wid & 3;                 // 4 x 16 rows
    int warpN = wid >> 2;                // 4 x 32 cols

    float acc[4][4];
#pragma unroll
    for (int nt = 0; nt < 4; nt++)
#pragma unroll
        for (int q = 0; q < 4; q++) acc[nt][q] = 0.f;

    uint32_t aoff = (uint32_t)((warpM * 16 + (lane & 15)) * TROWB + ((lane >> 4) * 8) * 2);
    int g = lane >> 3;
    uint32_t boff = (uint32_t)((warpN * 32 + (g >> 1) * 8 + (lane & 7)) * TROWB + (g & 1) * 16);

#pragma unroll
    for (int t = 0; t < 3; t++) {
        uint32_t abase = sbase + (t == 2 ? ALO_O : AHI_O) + aoff;
        uint32_t bbase = sbase + (t == 1 ? WLO_O : WHI_O) + boff;
#pragma unroll
        for (int ks = 0; ks < 8; ks++) {
            uint32_t af[4], bf[2][4];
            ldm_x4(af, abase + ks * 32);
#pragma unroll
            for (int np = 0; np < 2; np++)
                ldm_x4(bf[np], bbase + np * 16 * TROWB + ks * 32);
#pragma unroll
            for (int nt = 0; nt < 4; nt++)
                mma_bf16(acc[nt], af,
                         bf[nt >> 1][(nt & 1) * 2], bf[nt >> 1][(nt & 1) * 2 + 1]);
        }
    }

    // epilogue: scale rows by dinv, store fp16 g_h
    int crow = warpM * 16 + (lane >> 2);
    int ccol = warpN * 32 + (lane & 3) * 2;
    int r0 = row0 + crow;
    float d0 = (r0 < M)     ? __ldg(&g_dinv[r0])     : 0.f;
    float d1 = (r0 + 8 < M) ? __ldg(&g_dinv[r0 + 8]) : 0.f;
#pragma unroll
    for (int nt = 0; nt < 4; nt++) {
        int c = ccol + nt * 8;
        if (r0 < M) {
            float2 v0 = {d0 * acc[nt][0], d0 * acc[nt][1]};
            *(__half2*)(g_h + (size_t)r0 * FDIM + c) = __float22half2_rn(v0);
        }
        if (r0 + 8 < M) {
            float2 v1 = {d1 * acc[nt][2], d1 * acc[nt][3]};
            *(__half2*)(g_h + (size_t)(r0 + 8) * FDIM + c) = __float22half2_rn(v1);
        }
    }
}

// ---------------- Pull aggregation + bias + leaky_relu ----------------
// out_i = di*(sum_j h'_j) + di*h'_i + b with h' = dinv-scaled rows.
// one warp/node; half-warps take even/odd edges, unrolled x2.

__device__ __forceinline__ void unpack8(uint4 pk, float* f) {
    float2 a = __half22float2(*(const __half2*)&pk.x);
    float2 b = __half22float2(*(const __half2*)&pk.y);
    float2 c = __half22float2(*(const __half2*)&pk.z);
    float2 d = __half22float2(*(const __half2*)&pk.w);
    f[0] = a.x; f[1] = a.y; f[2] = b.x; f[3] = b.y;
    f[4] = c.x; f[5] = c.y; f[6] = d.x; f[7] = d.y;
}

__global__ __launch_bounds__(256)
void agg_kernel(const float* __restrict__ bias, float* __restrict__ outopt, int n) {
    int gtid = blockIdx.x * blockDim.x + threadIdx.x;
    int node = gtid >> 5;
    int lane = threadIdx.x & 31;
    if (node >= n) return;
    int half = lane >> 4;
    int fl = lane & 15;

    float di  = g_dinv[node];
    int beg = g_off[node], end = g_off[node + 1];
    float acc[8] = {0.f, 0.f, 0.f, 0.f, 0.f, 0.f, 0.f, 0.f};

    int e = beg + half;
    while (e + 2 < end) {
        int ja = g_csr[e];
        int jb = g_csr[e + 2];
        uint4 pa = __ldg((const uint4*)(g_h + (size_t)ja * FDIM + fl * 8));
        uint4 pb = __ldg((const uint4*)(g_h + (size_t)jb * FDIM + fl * 8));
        float fa[8]; unpack8(pa, fa);
        float fb[8]; unpack8(pb, fb);
#pragma unroll
        for (int q = 0; q < 8; q++) acc[q] += fa[q] + fb[q];
        e += 4;
    }
    if (e < end) {
        int j = g_csr[e];
        uint4 pk = __ldg((const uint4*)(g_h + (size_t)j * FDIM + fl * 8));
        float p[8]; unpack8(pk, p);
#pragma unroll
        for (int q = 0; q < 8; q++) acc[q] += p[q];
    }
#pragma unroll
    for (int q = 0; q < 8; q++) acc[q] += __shfl_xor_sync(0xffffffffu, acc[q], 16);

    uint4 hk = __ldg((const uint4*)(g_h + (size_t)node * FDIM + fl * 8));
    float hs[8]; unpack8(hk, hs);
    float4 bb0 = __ldg((const float4*)(bias + fl * 8));
    float4 bb1 = __ldg((const float4*)(bias + fl * 8 + 4));
    float bv[8] = {bb0.x, bb0.y, bb0.z, bb0.w, bb1.x, bb1.y, bb1.z, bb1.w};
    float o[8];
#pragma unroll
    for (int q = 0; q < 8; q++) {
        float v = di * (acc[q] + hs[q]) + bv[q];
        o[q] = v > 0.f ? v : 0.01f * v;
    }
    if (half == 0) {
        if (outopt) {
            float4 s0 = {o[0], o[1], o[2], o[3]};
            float4 s1 = {o[4], o[5], o[6], o[7]};
            *(float4*)(outopt + (size_t)node * FDIM + fl * 8)     = s0;
            *(float4*)(outopt + (size_t)node * FDIM + fl * 8 + 4) = s1;
        } else {
            uint4 s;
            float2 t0 = {o[0], o[1]}, t1 = {o[2], o[3]};
            float2 t2 = {o[4], o[5]}, t3 = {o[6], o[7]};
            __half2 q0 = __float22half2_rn(t0), q1 = __float22half2_rn(t1);
            __half2 q2 = __float22half2_rn(t2), q3 = __float22half2_rn(t3);
            s.x = *(uint32_t*)&q0; s.y = *(uint32_t*)&q1;
            s.z = *(uint32_t*)&q2; s.w = *(uint32_t*)&q3;
            *(uint4*)(g_yh + (size_t)node * FDIM + fl * 8) = s;
        }
    }
}

// ---------------- launch ----------------

extern "C" void kernel_launch(void* const* d_in, const int* in_sizes, int n_in,
                              void* d_out, int out_size) {
    const float* x  = (const float*)d_in[0];
    const void*  ei = d_in[1];
    const float* W1 = (const float*)d_in[2];
    const float* b1 = (const float*)d_in[3];
    const float* W2 = (const float*)d_in[4];
    const float* b2 = (const float*)d_in[5];
    float*       out = (float*)d_out;

    int N = in_sizes[0] / FDIM;        // 100000
    int E = in_sizes[1] / 2;           // 1600000

    int nB = (N + 255) / 256;
    int eB = (E + 255) / 256;
    int gemmB = (N + 63) / 64;
    int aggB  = (N * 32 + 255) / 256;

    cudaFuncSetAttribute(gemm_mma_kernel,
                         cudaFuncAttributeMaxDynamicSharedMemorySize, SM_TOT);

    static cudaStream_t s2;
    static cudaEvent_t evFork, evDinv, evCsr;
    static bool init = false;
    if (!init) {
        cudaStreamCreateWithFlags(&s2, cudaStreamNonBlocking);
        cudaEventCreateWithFlags(&evFork, cudaEventDisableTiming);
        cudaEventCreateWithFlags(&evDinv, cudaEventDisableTiming);
        cudaEventCreateWithFlags(&evCsr, cudaEventDisableTiming);
        init = true;
    }

    // fork: CSR chain on s2
    cudaEventRecord(evFork, 0);
    cudaStreamWaitEvent(s2, evFork, 0);

    dz_kernel<<<nB, 256, 0, s2>>>((const unsigned int*)ei, N);
    deg_kernel<<<eB, 256, 0, s2>>>(ei, E, N);
    scan1_kernel<<<SCAN_NB, SCAN_B, 0, s2>>>(N);      // also computes dinv
    cudaEventRecord(evDinv, s2);
    scan3_kernel<<<SCAN_NB, SCAN_B, 0, s2>>>(SCAN_NB, N, E);
    scatter_kernel<<<eB, 256, 0, s2>>>(ei, E, N);
    cudaEventRecord(evCsr, s2);

    // main: GEMM1 (needs dinv) overlaps scan3/scatter
    cudaStreamWaitEvent(0, evDinv, 0);
    gemm_mma_kernel<<<gemmB, 512, SM_TOT>>>(x, W1, N);

    cudaStreamWaitEvent(0, evCsr, 0);
    agg_kernel<<<aggB, 256>>>(b1, nullptr, N);          // -> fp16 g_yh
    gemm_mma_kernel<<<gemmB, 512, SM_TOT>>>(nullptr, W2, N);
    agg_kernel<<<aggB, 256>>>(b2, out, N);              // -> fp32 out
}

// round 15
// speedup vs baseline: 1.2419x; 1.2419x over previous
#include <cuda_runtime.h>
#include <cuda_bf16.h>
#include <cuda_fp16.h>
#include <cstdint>

// ---------------------------------------------------------------------------
// GCN 2-layer encoder. CSR per call (overlapped with layer-1 GEMM); GEMM
// epilogue pre-scales rows by dinv so aggregation is a pure row-sum; fp16
// h / inter-layer activation; bf16x3 mma.sync GEMM, BM=128 (best measured).
// ---------------------------------------------------------------------------

#define N_NODES 100000
#define N_EDGES 1600000
#define FDIM    128
#define SCAN_B  1024
#define SCAN_NB ((N_NODES + SCAN_B - 1) / SCAN_B)   // 98

__device__ int    g_is64;
__device__ int    g_deg[N_NODES];
__device__ int    g_pos[N_NODES];
__device__ int    g_off[N_NODES + 1];
__device__ int    g_bsum[SCAN_NB];
__device__ float  g_dinv[N_NODES];
__device__ int    g_csr[N_EDGES];
__device__ __half g_h[(size_t)N_NODES * FDIM];    // dinv-scaled GEMM output
__device__ __half g_yh[(size_t)N_NODES * FDIM];   // layer-1 activation (fp16)

// ---------------- detect dtype + zero counters (fused) ----------------
__global__ void dz_kernel(const unsigned int* __restrict__ w, int n) {
    int i = blockIdx.x * blockDim.x + threadIdx.x;
    if (i < n) g_deg[i] = 0;
    if (blockIdx.x == 0) {
        int z = (w[2 * threadIdx.x + 1] == 0u) ? 1 : 0;
        int total = __syncthreads_count(z);
        if (threadIdx.x == 0) g_is64 = (total == 256) ? 1 : 0;
    }
}

__device__ __forceinline__ int edge_at(const void* ei, long long idx, int n) {
    long long v = g_is64 ? ((const long long*)ei)[idx]
                         : (long long)((const int*)ei)[idx];
    int i = (int)v;
    if (i < 0) i = 0;
    if (i >= n) i = n - 1;
    return i;
}

// ---------------- CSR build ----------------

__global__ void deg_kernel(const void* __restrict__ ei, int E, int n) {
    int e = blockIdx.x * blockDim.x + threadIdx.x;
    if (e < E) atomicAdd(&g_deg[edge_at(ei, (long long)E + e, n)], 1);
}

// per-block scan of counts + dinv computation (fused)
__global__ void scan1_kernel(int n) {
    __shared__ int s[SCAN_B];
    int t = threadIdx.x;
    int i = blockIdx.x * SCAN_B + t;
    int v = 0;
    if (i < n) {
        v = g_deg[i];
        g_dinv[i] = rsqrtf((float)v + 1.0f);
    }
    s[t] = v;
    __syncthreads();
    for (int o = 1; o < SCAN_B; o <<= 1) {
        int x = (t >= o) ? s[t - o] : 0;
        __syncthreads();
        s[t] += x;
        __syncthreads();
    }
    if (i < n) g_off[i] = s[t] - v;
    if (t == SCAN_B - 1) g_bsum[blockIdx.x] = s[t];
}

// finalize offsets: every block redundantly scans the 98 block sums (L2-hot),
// adds its exclusive prefix, seeds the scatter cursor.
__global__ void scan3_kernel(int nb, int n, int E) {
    __shared__ int s[128];
    __shared__ int pre;
    int t = threadIdx.x;
    if (t < 128) {
        int v = (t < nb) ? g_bsum[t] : 0;
        s[t] = v;
    }
    __syncthreads();
    if (t < 128) {
        for (int o = 1; o < 128; o <<= 1) {
            int x = (t >= o) ? s[t - o] : 0;
            __syncthreads();
            s[t] += x;
            __syncthreads();
        }
        if (t == 0) pre = (blockIdx.x == 0) ? 0 : s[blockIdx.x - 1];
    } else {
        for (int o = 1; o < 128; o <<= 1) { __syncthreads(); __syncthreads(); }
    }
    __syncthreads();
    int base = pre;
    int i = blockIdx.x * SCAN_B + t;
    if (i < n) {
        int o = g_off[i] + base;
        g_off[i] = o;
        g_pos[i] = o;
    }
    if (i == n - 1) g_off[n] = E;
}

__global__ void scatter_kernel(const void* __restrict__ ei, int E, int n) {
    int e = blockIdx.x * blockDim.x + threadIdx.x;
    if (e < E) {
        int s = edge_at(ei, e, n);
        int d = edge_at(ei, (long long)E + e, n);
        g_csr[atomicAdd(&g_pos[d], 1)] = s;
    }
}

// ---------------- mma.sync bf16x3 GEMM, BM=128 -----------------------------
// g_h[M,128](fp16) = dinv[:,None] * (A @ W^T). A fp32 or fp16 g_yh.
// 512 threads, 16 warps, each a 32x32 C-tile. 272B rows: conflict-free.

#define TROWB 272
#define TSZ   (128 * TROWB)
#define AHI_O 0
#define ALO_O (TSZ)
#define WHI_O (2 * TSZ)
#define WLO_O (3 * TSZ)
#define SM_TOT (4 * TSZ)                 // 139264 B dynamic smem

__device__ __forceinline__ uint32_t smem_u32(const void* p) {
    uint32_t a;
    asm("{ .reg .u64 t; cvta.to.shared.u64 t, %1; cvt.u32.u64 %0, t; }"
        : "=r"(a) : "l"(p));
    return a;
}

__device__ __forceinline__ uint32_t pack_bf2(__nv_bfloat16 a, __nv_bfloat16 b) {
    return (uint32_t)__bfloat16_as_ushort(a) | ((uint32_t)__bfloat16_as_ushort(b) << 16);
}

__device__ __forceinline__ void cvt_store(char* smem, int hi_off, int lo_off,
                                          int r, int c4, float4 v) {
    __nv_bfloat16 h0 = __float2bfloat16_rn(v.x);
    __nv_bfloat16 h1 = __float2bfloat16_rn(v.y);
    __nv_bfloat16 h2 = __float2bfloat16_rn(v.z);
    __nv_bfloat16 h3 = __float2bfloat16_rn(v.w);
    __nv_bfloat16 l0 = __float2bfloat16_rn(v.x - __bfloat162float(h0));
    __nv_bfloat16 l1 = __float2bfloat16_rn(v.y - __bfloat162float(h1));
    __nv_bfloat16 l2 = __float2bfloat16_rn(v.z - __bfloat162float(h2));
    __nv_bfloat16 l3 = __float2bfloat16_rn(v.w - __bfloat162float(h3));
    int off = r * TROWB + c4 * 2;
    uint2 hp; hp.x = pack_bf2(h0, h1); hp.y = pack_bf2(h2, h3);
    uint2 lp; lp.x = pack_bf2(l0, l1); lp.y = pack_bf2(l2, l3);
    *(uint2*)(smem + hi_off + off) = hp;
    *(uint2*)(smem + lo_off + off) = lp;
}

__device__ __forceinline__ void ldm_x4(uint32_t* r, uint32_t addr) {
    asm volatile("ldmatrix.sync.aligned.m8n8.x4.shared.b16 {%0,%1,%2,%3}, [%4];"
                 : "=r"(r[0]), "=r"(r[1]), "=r"(r[2]), "=r"(r[3]) : "r"(addr));
}

__device__ __forceinline__ void mma_bf16(float* c, const uint32_t* a,
                                         uint32_t b0, uint32_t b1) {
    asm volatile(
        "mma.sync.aligned.m16n8k16.row.col.f32.bf16.bf16.f32 "
        "{%0,%1,%2,%3}, {%4,%5,%6,%7}, {%8,%9}, {%0,%1,%2,%3};"
        : "+f"(c[0]), "+f"(c[1]), "+f"(c[2]), "+f"(c[3])
        : "r"(a[0]), "r"(a[1]), "r"(a[2]), "r"(a[3]), "r"(b0), "r"(b1));
}

__global__ __launch_bounds__(512, 1)
void gemm_mma_kernel(const float* __restrict__ Aopt, const float* __restrict__ W,
                     int M) {
    extern __shared__ char smem[];
    int tid = threadIdx.x;
    int wid = tid >> 5;
    int lane = tid & 31;
    int row0 = blockIdx.x * 128;
    int trows = (row0 + 128 <= M) ? 128 : (M - row0);

    for (int idx = tid; idx < 128 * 32; idx += 512) {
        int r = idx >> 5;
        int c4 = (idx & 31) << 2;
        float4 v = {0.f, 0.f, 0.f, 0.f};
        if (r < trows) {
            if (Aopt) {
                v = *(const float4*)(Aopt + (size_t)(row0 + r) * FDIM + c4);
            } else {
                uint2 pk = *(const uint2*)(g_yh + (size_t)(row0 + r) * FDIM + c4);
                float2 a = __half22float2(*(const __half2*)&pk.x);
                float2 b = __half22float2(*(const __half2*)&pk.y);
                v.x = a.x; v.y = a.y; v.z = b.x; v.w = b.y;
            }
        }
        cvt_store(smem, AHI_O, ALO_O, r, c4, v);
        float4 wv = *(const float4*)(W + (size_t)r * FDIM + c4);
        cvt_store(smem, WHI_O, WLO_O, r, c4, wv);
    }
    __syncthreads();

    uint32_t sbase = smem_u32(smem);
    int warpM = wid & 3;
    int warpN = wid >> 2;

    float acc[2][4][4];
#pragma unroll
    for (int mt = 0; mt < 2; mt++)
#pragma unroll
        for (int nt = 0; nt < 4; nt++)
#pragma unroll
            for (int q = 0; q < 4; q++) acc[mt][nt][q] = 0.f;

    uint32_t aoff = (uint32_t)((warpM * 32 + (lane & 15)) * TROWB + ((lane >> 4) * 8) * 2);
    int g = lane >> 3;
    uint32_t boff = (uint32_t)((warpN * 32 + (g >> 1) * 8 + (lane & 7)) * TROWB + (g & 1) * 16);

#pragma unroll
    for (int t = 0; t < 3; t++) {
        uint32_t abase = sbase + (t == 2 ? ALO_O : AHI_O) + aoff;
        uint32_t bbase = sbase + (t == 1 ? WLO_O : WHI_O) + boff;
#pragma unroll
        for (int ks = 0; ks < 8; ks++) {
            uint32_t af[2][4], bf[2][4];
            ldm_x4(af[0], abase + ks * 32);
            ldm_x4(af[1], abase + 16 * TROWB + ks * 32);
#pragma unroll
            for (int np = 0; np < 2; np++)
                ldm_x4(bf[np], bbase + np * 16 * TROWB + ks * 32);
#pragma unroll
            for (int mt = 0; mt < 2; mt++)
#pragma unroll
                for (int nt = 0; nt < 4; nt++)
                    mma_bf16(acc[mt][nt], af[mt],
                             bf[nt >> 1][(nt & 1) * 2], bf[nt >> 1][(nt & 1) * 2 + 1]);
        }
    }

    int crow = warpM * 32 + (lane >> 2);
    int ccol = warpN * 32 + (lane & 3) * 2;
#pragma unroll
    for (int mt = 0; mt < 2; mt++) {
        int r0 = row0 + crow + mt * 16;
        float d0 = (r0 < M)     ? __ldg(&g_dinv[r0])     : 0.f;
        float d1 = (r0 + 8 < M) ? __ldg(&g_dinv[r0 + 8]) : 0.f;
#pragma unroll
        for (int nt = 0; nt < 4; nt++) {
            int c = ccol + nt * 8;
            if (r0 < M) {
                float2 v0 = {d0 * acc[mt][nt][0], d0 * acc[mt][nt][1]};
                *(__half2*)(g_h + (size_t)r0 * FDIM + c) = __float22half2_rn(v0);
            }
            if (r0 + 8 < M) {
                float2 v1 = {d1 * acc[mt][nt][2], d1 * acc[mt][nt][3]};
                *(__half2*)(g_h + (size_t)(r0 + 8) * FDIM + c) = __float22half2_rn(v1);
            }
        }
    }
}

// ---------------- Pull aggregation + bias + leaky_relu ----------------
// out_i = di*(sum_j h'_j) + di*h'_i + b with h' = dinv-scaled rows.
// one warp/node; half-warps take even/odd edges, unrolled x2.

__device__ __forceinline__ void unpack8(uint4 pk, float* f) {
    float2 a = __half22float2(*(const __half2*)&pk.x);
    float2 b = __half22float2(*(const __half2*)&pk.y);
    float2 c = __half22float2(*(const __half2*)&pk.z);
    float2 d = __half22float2(*(const __half2*)&pk.w);
    f[0] = a.x; f[1] = a.y; f[2] = b.x; f[3] = b.y;
    f[4] = c.x; f[5] = c.y; f[6] = d.x; f[7] = d.y;
}

__global__ __launch_bounds__(256)
void agg_kernel(const float* __restrict__ bias, float* __restrict__ outopt, int n) {
    int gtid = blockIdx.x * blockDim.x + threadIdx.x;
    int node = gtid >> 5;
    int lane = threadIdx.x & 31;
    if (node >= n) return;
    int half = lane >> 4;
    int fl = lane & 15;

    float di  = g_dinv[node];
    int beg = g_off[node], end = g_off[node + 1];
    float acc[8] = {0.f, 0.f, 0.f, 0.f, 0.f, 0.f, 0.f, 0.f};

    int e = beg + half;
    while (e + 2 < end) {
        int ja = g_csr[e];
        int jb = g_csr[e + 2];
        uint4 pa = __ldg((const uint4*)(g_h + (size_t)ja * FDIM + fl * 8));
        uint4 pb = __ldg((const uint4*)(g_h + (size_t)jb * FDIM + fl * 8));
        float fa[8]; unpack8(pa, fa);
        float fb[8]; unpack8(pb, fb);
#pragma unroll
        for (int q = 0; q < 8; q++) acc[q] += fa[q] + fb[q];
        e += 4;
    }
    if (e < end) {
        int j = g_csr[e];
        uint4 pk = __ldg((const uint4*)(g_h + (size_t)j * FDIM + fl * 8));
        float p[8]; unpack8(pk, p);
#pragma unroll
        for (int q = 0; q < 8; q++) acc[q] += p[q];
    }
#pragma unroll
    for (int q = 0; q < 8; q++) acc[q] += __shfl_xor_sync(0xffffffffu, acc[q], 16);

    uint4 hk = __ldg((const uint4*)(g_h + (size_t)node * FDIM + fl * 8));
    float hs[8]; unpack8(hk, hs);
    float4 bb0 = __ldg((const float4*)(bias + fl * 8));
    float4 bb1 = __ldg((const float4*)(bias + fl * 8 + 4));
    float bv[8] = {bb0.x, bb0.y, bb0.z, bb0.w, bb1.x, bb1.y, bb1.z, bb1.w};
    float o[8];
#pragma unroll
    for (int q = 0; q < 8; q++) {
        float v = di * (acc[q] + hs[q]) + bv[q];
        o[q] = v > 0.f ? v : 0.01f * v;
    }
    if (half == 0) {
        if (outopt) {
            float4 s0 = {o[0], o[1], o[2], o[3]};
            float4 s1 = {o[4], o[5], o[6], o[7]};
            *(float4*)(outopt + (size_t)node * FDIM + fl * 8)     = s0;
            *(float4*)(outopt + (size_t)node * FDIM + fl * 8 + 4) = s1;
        } else {
            uint4 s;
            float2 t0 = {o[0], o[1]}, t1 = {o[2], o[3]};
            float2 t2 = {o[4], o[5]}, t3 = {o[6], o[7]};
            __half2 q0 = __float22half2_rn(t0), q1 = __float22half2_rn(t1);
            __half2 q2 = __float22half2_rn(t2), q3 = __float22half2_rn(t3);
            s.x = *(uint32_t*)&q0; s.y = *(uint32_t*)&q1;
            s.z = *(uint32_t*)&q2; s.w = *(uint32_t*)&q3;
            *(uint4*)(g_yh + (size_t)node * FDIM + fl * 8) = s;
        }
    }
}

// ---------------- launch ----------------

extern "C" void kernel_launch(void* const* d_in, const int* in_sizes, int n_in,
                              void* d_out, int out_size) {
    const float* x  = (const float*)d_in[0];
    const void*  ei = d_in[1];
    const float* W1 = (const float*)d_in[2];
    const float* b1 = (const float*)d_in[3];
    const float* W2 = (const float*)d_in[4];
    const float* b2 = (const float*)d_in[5];
    float*       out = (float*)d_out;

    int N = in_sizes[0] / FDIM;        // 100000
    int E = in_sizes[1] / 2;           // 1600000

    int nB = (N + 255) / 256;
    int eB = (E + 255) / 256;
    int gemmB = (N + 127) / 128;
    int aggB  = (N * 32 + 255) / 256;

    cudaFuncSetAttribute(gemm_mma_kernel,
                         cudaFuncAttributeMaxDynamicSharedMemorySize, SM_TOT);

    static cudaStream_t s2;
    static cudaEvent_t evFork, evDinv, evCsr;
    static bool init = false;
    if (!init) {
        cudaStreamCreateWithFlags(&s2, cudaStreamNonBlocking);
        cudaEventCreateWithFlags(&evFork, cudaEventDisableTiming);
        cudaEventCreateWithFlags(&evDinv, cudaEventDisableTiming);
        cudaEventCreateWithFlags(&evCsr, cudaEventDisableTiming);
        init = true;
    }

    // fork: CSR chain on s2
    cudaEventRecord(evFork, 0);
    cudaStreamWaitEvent(s2, evFork, 0);

    dz_kernel<<<nB, 256, 0, s2>>>((const unsigned int*)ei, N);
    deg_kernel<<<eB, 256, 0, s2>>>(ei, E, N);
    scan1_kernel<<<SCAN_NB, SCAN_B, 0, s2>>>(N);      // also computes dinv
    cudaEventRecord(evDinv, s2);
    scan3_kernel<<<SCAN_NB, SCAN_B, 0, s2>>>(SCAN_NB, N, E);
    scatter_kernel<<<eB, 256, 0, s2>>>(ei, E, N);
    cudaEventRecord(evCsr, s2);

    // main: GEMM1 (needs dinv) overlaps scan3/scatter
    cudaStreamWaitEvent(0, evDinv, 0);
    gemm_mma_kernel<<<gemmB, 512, SM_TOT>>>(x, W1, N);

    cudaStreamWaitEvent(0, evCsr, 0);
    agg_kernel<<<aggB, 256>>>(b1, nullptr, N);          // -> fp16 g_yh
    gemm_mma_kernel<<<gemmB, 512, SM_TOT>>>(nullptr, W2, N);
    agg_kernel<<<aggB, 256>>>(b2, out, N);              // -> fp32 out
}

// round 17
// speedup vs baseline: 1.3129x; 1.0571x over previous
#include <cuda_runtime.h>
#include <cuda_bf16.h>
#include <cuda_fp16.h>
#include <cstdint>

// ---------------------------------------------------------------------------
// GCN 2-layer encoder. CSR per call (overlapped with layer-1 GEMM); GEMM
// epilogue pre-scales rows by dinv so aggregation is a pure row-sum; fp16
// h / inter-layer activation; bf16x3 mma.sync GEMM BM=128. Agg loop uses
// R9's cross-iteration csr prefetch (unroll-x2 variant regressed; reverted).
// ---------------------------------------------------------------------------

#define N_NODES 100000
#define N_EDGES 1600000
#define FDIM    128
#define SCAN_B  1024
#define SCAN_NB ((N_NODES + SCAN_B - 1) / SCAN_B)   // 98

__device__ int    g_is64;
__device__ int    g_deg[N_NODES];
__device__ int    g_pos[N_NODES];
__device__ int    g_off[N_NODES + 1];
__device__ int    g_bsum[SCAN_NB];
__device__ float  g_dinv[N_NODES];
__device__ int    g_csr[N_EDGES];
__device__ __half g_h[(size_t)N_NODES * FDIM];    // dinv-scaled GEMM output
__device__ __half g_yh[(size_t)N_NODES * FDIM];   // layer-1 activation (fp16)

// ---------------- detect dtype + zero counters (fused) ----------------
__global__ void dz_kernel(const unsigned int* __restrict__ w, int n) {
    int i = blockIdx.x * blockDim.x + threadIdx.x;
    if (i < n) g_deg[i] = 0;
    if (blockIdx.x == 0) {
        int z = (w[2 * threadIdx.x + 1] == 0u) ? 1 : 0;
        int total = __syncthreads_count(z);
        if (threadIdx.x == 0) g_is64 = (total == 256) ? 1 : 0;
    }
}

__device__ __forceinline__ int edge_at(const void* ei, long long idx, int n) {
    long long v = g_is64 ? ((const long long*)ei)[idx]
                         : (long long)((const int*)ei)[idx];
    int i = (int)v;
    if (i < 0) i = 0;
    if (i >= n) i = n - 1;
    return i;
}

// ---------------- CSR build ----------------

__global__ void deg_kernel(const void* __restrict__ ei, int E, int n) {
    int e = blockIdx.x * blockDim.x + threadIdx.x;
    if (e < E) atomicAdd(&g_deg[edge_at(ei, (long long)E + e, n)], 1);
}

// per-block scan of counts + dinv computation (fused)
__global__ void scan1_kernel(int n) {
    __shared__ int s[SCAN_B];
    int t = threadIdx.x;
    int i = blockIdx.x * SCAN_B + t;
    int v = 0;
    if (i < n) {
        v = g_deg[i];
        g_dinv[i] = rsqrtf((float)v + 1.0f);
    }
    s[t] = v;
    __syncthreads();
    for (int o = 1; o < SCAN_B; o <<= 1) {
        int x = (t >= o) ? s[t - o] : 0;
        __syncthreads();
        s[t] += x;
        __syncthreads();
    }
    if (i < n) g_off[i] = s[t] - v;
    if (t == SCAN_B - 1) g_bsum[blockIdx.x] = s[t];
}

// finalize offsets: every block redundantly scans the 98 block sums (L2-hot),
// adds its exclusive prefix, seeds the scatter cursor.
__global__ void scan3_kernel(int nb, int n, int E) {
    __shared__ int s[128];
    __shared__ int pre;
    int t = threadIdx.x;
    if (t < 128) {
        int v = (t < nb) ? g_bsum[t] : 0;
        s[t] = v;
    }
    __syncthreads();
    if (t < 128) {
        for (int o = 1; o < 128; o <<= 1) {
            int x = (t >= o) ? s[t - o] : 0;
            __syncthreads();
            s[t] += x;
            __syncthreads();
        }
        if (t == 0) pre = (blockIdx.x == 0) ? 0 : s[blockIdx.x - 1];
    } else {
        for (int o = 1; o < 128; o <<= 1) { __syncthreads(); __syncthreads(); }
    }
    __syncthreads();
    int base = pre;
    int i = blockIdx.x * SCAN_B + t;
    if (i < n) {
        int o = g_off[i] + base;
        g_off[i] = o;
        g_pos[i] = o;
    }
    if (i == n - 1) g_off[n] = E;
}

__global__ void scatter_kernel(const void* __restrict__ ei, int E, int n) {
    int e = blockIdx.x * blockDim.x + threadIdx.x;
    if (e < E) {
        int s = edge_at(ei, e, n);
        int d = edge_at(ei, (long long)E + e, n);
        g_csr[atomicAdd(&g_pos[d], 1)] = s;
    }
}

// ---------------- mma.sync bf16x3 GEMM, BM=128 -----------------------------
// g_h[M,128](fp16) = dinv[:,None] * (A @ W^T). A fp32 or fp16 g_yh.
// 512 threads, 16 warps, each a 32x32 C-tile. 272B rows: conflict-free.

#define TROWB 272
#define TSZ   (128 * TROWB)
#define AHI_O 0
#define ALO_O (TSZ)
#define WHI_O (2 * TSZ)
#define WLO_O (3 * TSZ)
#define SM_TOT (4 * TSZ)                 // 139264 B dynamic smem

__device__ __forceinline__ uint32_t smem_u32(const void* p) {
    uint32_t a;
    asm("{ .reg .u64 t; cvta.to.shared.u64 t, %1; cvt.u32.u64 %0, t; }"
        : "=r"(a) : "l"(p));
    return a;
}

__device__ __forceinline__ uint32_t pack_bf2(__nv_bfloat16 a, __nv_bfloat16 b) {
    return (uint32_t)__bfloat16_as_ushort(a) | ((uint32_t)__bfloat16_as_ushort(b) << 16);
}

__device__ __forceinline__ void cvt_store(char* smem, int hi_off, int lo_off,
                                          int r, int c4, float4 v) {
    __nv_bfloat16 h0 = __float2bfloat16_rn(v.x);
    __nv_bfloat16 h1 = __float2bfloat16_rn(v.y);
    __nv_bfloat16 h2 = __float2bfloat16_rn(v.z);
    __nv_bfloat16 h3 = __float2bfloat16_rn(v.w);
    __nv_bfloat16 l0 = __float2bfloat16_rn(v.x - __bfloat162float(h0));
    __nv_bfloat16 l1 = __float2bfloat16_rn(v.y - __bfloat162float(h1));
    __nv_bfloat16 l2 = __float2bfloat16_rn(v.z - __bfloat162float(h2));
    __nv_bfloat16 l3 = __float2bfloat16_rn(v.w - __bfloat162float(h3));
    int off = r * TROWB + c4 * 2;
    uint2 hp; hp.x = pack_bf2(h0, h1); hp.y = pack_bf2(h2, h3);
    uint2 lp; lp.x = pack_bf2(l0, l1); lp.y = pack_bf2(l2, l3);
    *(uint2*)(smem + hi_off + off) = hp;
    *(uint2*)(smem + lo_off + off) = lp;
}

__device__ __forceinline__ void ldm_x4(uint32_t* r, uint32_t addr) {
    asm volatile("ldmatrix.sync.aligned.m8n8.x4.shared.b16 {%0,%1,%2,%3}, [%4];"
                 : "=r"(r[0]), "=r"(r[1]), "=r"(r[2]), "=r"(r[3]) : "r"(addr));
}

__device__ __forceinline__ void mma_bf16(float* c, const uint32_t* a,
                                         uint32_t b0, uint32_t b1) {
    asm volatile(
        "mma.sync.aligned.m16n8k16.row.col.f32.bf16.bf16.f32 "
        "{%0,%1,%2,%3}, {%4,%5,%6,%7}, {%8,%9}, {%0,%1,%2,%3};"
        : "+f"(c[0]), "+f"(c[1]), "+f"(c[2]), "+f"(c[3])
        : "r"(a[0]), "r"(a[1]), "r"(a[2]), "r"(a[3]), "r"(b0), "r"(b1));
}

__global__ __launch_bounds__(512, 1)
void gemm_mma_kernel(const float* __restrict__ Aopt, const float* __restrict__ W,
                     int M) {
    extern __shared__ char smem[];
    int tid = threadIdx.x;
    int wid = tid >> 5;
    int lane = tid & 31;
    int row0 = blockIdx.x * 128;
    int trows = (row0 + 128 <= M) ? 128 : (M - row0);

    for (int idx = tid; idx < 128 * 32; idx += 512) {
        int r = idx >> 5;
        int c4 = (idx & 31) << 2;
        float4 v = {0.f, 0.f, 0.f, 0.f};
        if (r < trows) {
            if (Aopt) {
                v = *(const float4*)(Aopt + (size_t)(row0 + r) * FDIM + c4);
            } else {
                uint2 pk = *(const uint2*)(g_yh + (size_t)(row0 + r) * FDIM + c4);
                float2 a = __half22float2(*(const __half2*)&pk.x);
                float2 b = __half22float2(*(const __half2*)&pk.y);
                v.x = a.x; v.y = a.y; v.z = b.x; v.w = b.y;
            }
        }
        cvt_store(smem, AHI_O, ALO_O, r, c4, v);
        float4 wv = *(const float4*)(W + (size_t)r * FDIM + c4);
        cvt_store(smem, WHI_O, WLO_O, r, c4, wv);
    }
    __syncthreads();

    uint32_t sbase = smem_u32(smem);
    int warpM = wid & 3;
    int warpN = wid >> 2;

    float acc[2][4][4];
#pragma unroll
    for (int mt = 0; mt < 2; mt++)
#pragma unroll
        for (int nt = 0; nt < 4; nt++)
#pragma unroll
            for (int q = 0; q < 4; q++) acc[mt][nt][q] = 0.f;

    uint32_t aoff = (uint32_t)((warpM * 32 + (lane & 15)) * TROWB + ((lane >> 4) * 8) * 2);
    int g = lane >> 3;
    uint32_t boff = (uint32_t)((warpN * 32 + (g >> 1) * 8 + (lane & 7)) * TROWB + (g & 1) * 16);

#pragma unroll
    for (int t = 0; t < 3; t++) {
        uint32_t abase = sbase + (t == 2 ? ALO_O : AHI_O) + aoff;
        uint32_t bbase = sbase + (t == 1 ? WLO_O : WHI_O) + boff;
#pragma unroll
        for (int ks = 0; ks < 8; ks++) {
            uint32_t af[2][4], bf[2][4];
            ldm_x4(af[0], abase + ks * 32);
            ldm_x4(af[1], abase + 16 * TROWB + ks * 32);
#pragma unroll
            for (int np = 0; np < 2; np++)
                ldm_x4(bf[np], bbase + np * 16 * TROWB + ks * 32);
#pragma unroll
            for (int mt = 0; mt < 2; mt++)
#pragma unroll
                for (int nt = 0; nt < 4; nt++)
                    mma_bf16(acc[mt][nt], af[mt],
                             bf[nt >> 1][(nt & 1) * 2], bf[nt >> 1][(nt & 1) * 2 + 1]);
        }
    }

    int crow = warpM * 32 + (lane >> 2);
    int ccol = warpN * 32 + (lane & 3) * 2;
#pragma unroll
    for (int mt = 0; mt < 2; mt++) {
        int r0 = row0 + crow + mt * 16;
        float d0 = (r0 < M)     ? __ldg(&g_dinv[r0])     : 0.f;
        float d1 = (r0 + 8 < M) ? __ldg(&g_dinv[r0 + 8]) : 0.f;
#pragma unroll
        for (int nt = 0; nt < 4; nt++) {
            int c = ccol + nt * 8;
            if (r0 < M) {
                float2 v0 = {d0 * acc[mt][nt][0], d0 * acc[mt][nt][1]};
                *(__half2*)(g_h + (size_t)r0 * FDIM + c) = __float22half2_rn(v0);
            }
            if (r0 + 8 < M) {
                float2 v1 = {d1 * acc[mt][nt][2], d1 * acc[mt][nt][3]};
                *(__half2*)(g_h + (size_t)(r0 + 8) * FDIM + c) = __float22half2_rn(v1);
            }
        }
    }
}

// ---------------- Pull aggregation + bias + leaky_relu ----------------
// out_i = di*(sum_j h'_j) + di*h'_i + b with h' = dinv-scaled rows.
// one warp/node; half-warps take even/odd edges; next csr index prefetched
// so the index-load latency hides under the current row gather.

__device__ __forceinline__ void unpack8(uint4 pk, float* f) {
    float2 a = __half22float2(*(const __half2*)&pk.x);
    float2 b = __half22float2(*(const __half2*)&pk.y);
    float2 c = __half22float2(*(const __half2*)&pk.z);
    float2 d = __half22float2(*(const __half2*)&pk.w);
    f[0] = a.x; f[1] = a.y; f[2] = b.x; f[3] = b.y;
    f[4] = c.x; f[5] = c.y; f[6] = d.x; f[7] = d.y;
}

__global__ __launch_bounds__(256)
void agg_kernel(const float* __restrict__ bias, float* __restrict__ outopt, int n) {
    int gtid = blockIdx.x * blockDim.x + threadIdx.x;
    int node = gtid >> 5;
    int lane = threadIdx.x & 31;
    if (node >= n) return;
    int half = lane >> 4;
    int fl = lane & 15;

    float di  = g_dinv[node];
    int beg = g_off[node], end = g_off[node + 1];
    float acc[8] = {0.f, 0.f, 0.f, 0.f, 0.f, 0.f, 0.f, 0.f};

    int e = beg + half;
    int j = (e < end) ? g_csr[e] : 0;
    while (e < end) {
        int e2 = e + 2;
        int j2 = (e2 < end) ? g_csr[e2] : 0;
        uint4 pk = __ldg((const uint4*)(g_h + (size_t)j * FDIM + fl * 8));
        float p[8]; unpack8(pk, p);
#pragma unroll
        for (int q = 0; q < 8; q++) acc[q] += p[q];
        e = e2; j = j2;
    }
#pragma unroll
    for (int q = 0; q < 8; q++) acc[q] += __shfl_xor_sync(0xffffffffu, acc[q], 16);

    uint4 hk = __ldg((const uint4*)(g_h + (size_t)node * FDIM + fl * 8));
    float hs[8]; unpack8(hk, hs);
    float4 bb0 = __ldg((const float4*)(bias + fl * 8));
    float4 bb1 = __ldg((const float4*)(bias + fl * 8 + 4));
    float bv[8] = {bb0.x, bb0.y, bb0.z, bb0.w, bb1.x, bb1.y, bb1.z, bb1.w};
    float o[8];
#pragma unroll
    for (int q = 0; q < 8; q++) {
        float v = di * (acc[q] + hs[q]) + bv[q];
        o[q] = v > 0.f ? v : 0.01f * v;
    }
    if (half == 0) {
        if (outopt) {
            float4 s0 = {o[0], o[1], o[2], o[3]};
            float4 s1 = {o[4], o[5], o[6], o[7]};
            *(float4*)(outopt + (size_t)node * FDIM + fl * 8)     = s0;
            *(float4*)(outopt + (size_t)node * FDIM + fl * 8 + 4) = s1;
        } else {
            uint4 s;
            float2 t0 = {o[0], o[1]}, t1 = {o[2], o[3]};
            float2 t2 = {o[4], o[5]}, t3 = {o[6], o[7]};
            __half2 q0 = __float22half2_rn(t0), q1 = __float22half2_rn(t1);
            __half2 q2 = __float22half2_rn(t2), q3 = __float22half2_rn(t3);
            s.x = *(uint32_t*)&q0; s.y = *(uint32_t*)&q1;
            s.z = *(uint32_t*)&q2; s.w = *(uint32_t*)&q3;
            *(uint4*)(g_yh + (size_t)node * FDIM + fl * 8) = s;
        }
    }
}

// ---------------- launch ----------------

extern "C" void kernel_launch(void* const* d_in, const int* in_sizes, int n_in,
                              void* d_out, int out_size) {
    const float* x  = (const float*)d_in[0];
    const void*  ei = d_in[1];
    const float* W1 = (const float*)d_in[2];
    const float* b1 = (const float*)d_in[3];
    const float* W2 = (const float*)d_in[4];
    const float* b2 = (const float*)d_in[5];
    float*       out = (float*)d_out;

    int N = in_sizes[0] / FDIM;        // 100000
    int E = in_sizes[1] / 2;           // 1600000

    int nB = (N + 255) / 256;
    int eB = (E + 255) / 256;
    int gemmB = (N + 127) / 128;
    int aggB  = (N * 32 + 255) / 256;

    cudaFuncSetAttribute(gemm_mma_kernel,
                         cudaFuncAttributeMaxDynamicSharedMemorySize, SM_TOT);

    static cudaStream_t s2;
    static cudaEvent_t evFork, evDinv, evCsr;
    static bool init = false;
    if (!init) {
        cudaStreamCreateWithFlags(&s2, cudaStreamNonBlocking);
        cudaEventCreateWithFlags(&evFork, cudaEventDisableTiming);
        cudaEventCreateWithFlags(&evDinv, cudaEventDisableTiming);
        cudaEventCreateWithFlags(&evCsr, cudaEventDisableTiming);
        init = true;
    }

    // fork: CSR chain on s2
    cudaEventRecord(evFork, 0);
    cudaStreamWaitEvent(s2, evFork, 0);

    dz_kernel<<<nB, 256, 0, s2>>>((const unsigned int*)ei, N);
    deg_kernel<<<eB, 256, 0, s2>>>(ei, E, N);
    scan1_kernel<<<SCAN_NB, SCAN_B, 0, s2>>>(N);      // also computes dinv
    cudaEventRecord(evDinv, s2);
    scan3_kernel<<<SCAN_NB, SCAN_B, 0, s2>>>(SCAN_NB, N, E);
    scatter_kernel<<<eB, 256, 0, s2>>>(ei, E, N);
    cudaEventRecord(evCsr, s2);

    // main: GEMM1 (needs dinv) overlaps scan3/scatter
    cudaStreamWaitEvent(0, evDinv, 0);
    gemm_mma_kernel<<<gemmB, 512, SM_TOT>>>(x, W1, N);

    cudaStreamWaitEvent(0, evCsr, 0);
    agg_kernel<<<aggB, 256>>>(b1, nullptr, N);          // -> fp16 g_yh
    gemm_mma_kernel<<<gemmB, 512, SM_TOT>>>(nullptr, W2, N);
    agg_kernel<<<aggB, 256>>>(b2, out, N);              // -> fp32 out
}